// round 13
// baseline (speedup 1.0000x reference)
#include <cuda_runtime.h>
#include <cuda_bf16.h>
#include <math.h>
#include <stdint.h>

#define NLEV 16
#define P2 2654435761u
#define P3 805459861u

struct LevelParams {
    int          R[NLEV];
    unsigned int H[NLEV];
    int          O[NLEV];
    int          linear[NLEV];
};

// Weights pre-arranged in mma FRAGMENT order by the prep kernel:
// g_f1[q*32 + ln] = w1 B-fragment word for lane ln, q = nt*8 + term*4 + s*2 + r
// g_f2[q*32 + ln] = w2 B-fragment word for lane ln, q = s2*4 + term*2 + r
__device__ __align__(16) unsigned g_f1[2048];
__device__ __align__(16) unsigned g_f2[512];

// smem: A tile only, 256 rows x 128B (warp-private quarters)
#define SMEM_TOT 32768
#define SW128(o) ((o) ^ (((o) >> 3) & 0x70))

// ---------------- helpers ----------------
__device__ __forceinline__ uint32_t smem_to_u32(const void* p) {
    uint32_t a;
    asm("{ .reg .u64 t; cvta.to.shared.u64 t, %1; cvt.u32.u64 %0, t; }" : "=r"(a) : "l"(p));
    return a;
}
__device__ __forceinline__ unsigned long long pack2(float lo, float hi) {
    unsigned long long r;
    asm("mov.b64 %0, {%1, %2};" : "=l"(r) : "f"(lo), "f"(hi));
    return r;
}
__device__ __forceinline__ void unpack2(unsigned long long v, float &lo, float &hi) {
    asm("mov.b64 {%0, %1}, %2;" : "=f"(lo), "=f"(hi) : "l"(v));
}
__device__ __forceinline__ void ffma2(unsigned long long &d, unsigned long long a, unsigned long long b) {
    asm("fma.rn.f32x2 %0, %1, %2, %0;" : "+l"(d) : "l"(a), "l"(b));
}
__device__ __forceinline__ unsigned packbf(__nv_bfloat16 a, __nv_bfloat16 b) {
    __nv_bfloat162 t = __halves2bfloat162(a, b);   // lo16=a, hi16=b
    unsigned r; memcpy(&r, &t, 4); return r;
}
__device__ __forceinline__ unsigned cvt_pack_bf(float lo, float hi) {
    unsigned r;
    asm("cvt.rn.bf16x2.f32 %0, %1, %2;" : "=r"(r) : "f"(hi), "f"(lo));
    return r;
}
__device__ __forceinline__ float bflo_f(unsigned u) { return __uint_as_float(u << 16); }
__device__ __forceinline__ float bfhi_f(unsigned u) { return __uint_as_float(u & 0xffff0000u); }

__device__ __forceinline__ void ldsm_x4(unsigned& r0, unsigned& r1, unsigned& r2, unsigned& r3, uint32_t a) {
    asm volatile("ldmatrix.sync.aligned.m8n8.x4.shared.b16 {%0,%1,%2,%3}, [%4];"
        : "=r"(r0), "=r"(r1), "=r"(r2), "=r"(r3) : "r"(a));
}
__device__ __forceinline__ void mma_bf16(float* d, const unsigned* a, const unsigned* b) {
    asm volatile("mma.sync.aligned.m16n8k16.row.col.f32.bf16.bf16.f32 "
        "{%0,%1,%2,%3}, {%4,%5,%6,%7}, {%8,%9}, {%0,%1,%2,%3};"
        : "+f"(d[0]), "+f"(d[1]), "+f"(d[2]), "+f"(d[3])
        : "r"(a[0]), "r"(a[1]), "r"(a[2]), "r"(a[3]), "r"(b[0]), "r"(b[1]));
}

// ---------------- prep kernel: emit weights in fragment order ----------------
__global__ void prep_weights_kernel(const float* __restrict__ w1,
                                    const float* __restrict__ w2) {
    int i = blockIdx.x * 256 + threadIdx.x;
    if (i < 2048) {
        int q = i >> 5, ln = i & 31;
        int nt = q >> 3, term = (q >> 2) & 1, s = (q >> 1) & 1, r = q & 1;
        int j  = nt * 8 + (ln >> 2);            // hidden unit (n within tile nt)
        int k0 = 16 * s + 8 * r + (ln & 3) * 2; // input feature index
        float v0 = w1[k0 * 64 + j];             // w1 is [32,64] row-major
        float v1 = w1[(k0 + 1) * 64 + j];
        __nv_bfloat16 h0 = __float2bfloat16(v0), h1 = __float2bfloat16(v1);
        unsigned rr;
        if (!term) rr = packbf(h0, h1);
        else rr = packbf(__float2bfloat16(v0 - __bfloat162float(h0)),
                         __float2bfloat16(v1 - __bfloat162float(h1)));
        g_f1[i] = rr;
    } else if (i < 2560) {
        int k2 = i - 2048;
        int q = k2 >> 5, ln = k2 & 31;
        int s2 = q >> 2, term = (q >> 1) & 1, r = q & 1;
        int n  = ln >> 2;                        // output index 0..7
        int k0 = 16 * s2 + 8 * r + (ln & 3) * 2; // hidden index 0..63
        float v0 = w2[k0 * 8 + n];               // w2 is [64,8] row-major
        float v1 = w2[(k0 + 1) * 8 + n];
        __nv_bfloat16 h0 = __float2bfloat16(v0), h1 = __float2bfloat16(v1);
        unsigned rr;
        if (!term) rr = packbf(h0, h1);
        else rr = packbf(__float2bfloat16(v0 - __bfloat162float(h0)),
                         __float2bfloat16(v1 - __bfloat162float(h1)));
        g_f2[k2] = rr;
    }
}

// ---------------- encode helpers (proven) ----------------
__device__ __forceinline__ void setup_item(
    const float* __restrict__ xyz, float b, float inv2b, int p, int oc,
    float& ex, float& ey, float& ez, float& wt)
{
    float cx = (xyz[3 * p + 0] + b) * inv2b * 512.0f;
    float cy = (xyz[3 * p + 1] + b) * inv2b * 512.0f;
    float cz = (xyz[3 * p + 2] + b) * inv2b * 512.0f;
    int c0x = min(max((int)floorf(cx), 0), 511);
    int c0y = min(max((int)floorf(cy), 0), 511);
    int c0z = min(max((int)floorf(cz), 0), 511);
    float u = cx - (float)c0x, v = cy - (float)c0y, w = cz - (float)c0z;
    int ox = (oc >> 2) & 1, oy = (oc >> 1) & 1, oz = oc & 1;
    wt = (ox ? u : 1.0f - u) * (oy ? v : 1.0f - v) * (oz ? w : 1.0f - w);
    ex = (float)(c0x + ox) * (1.0f / 512.0f);
    ey = (float)(c0y + oy) * (1.0f / 512.0f);
    ez = (float)(c0z + oz) * (1.0f / 512.0f);
}
struct LevWts {
    float wx0, fx;
    float wyz00, wyz01, wyz10, wyz11;
    int ix, iy, iz;
};
__device__ __forceinline__ LevWts level_setup(float Rf, float ex, float ey, float ez) {
    LevWts s;
    float px = ex * Rf + 0.5f, py = ey * Rf + 0.5f, pz = ez * Rf + 0.5f;
    float pgx = floorf(px), pgy = floorf(py), pgz = floorf(pz);
    float fx = px - pgx, fy = py - pgy, fz = pz - pgz;
    s.ix = (int)pgx; s.iy = (int)pgy; s.iz = (int)pgz;
    s.fx = fx; s.wx0 = 1.0f - fx;
    float wy0 = 1.0f - fy, wz0 = 1.0f - fz;
    s.wyz00 = wy0 * wz0; s.wyz01 = wy0 * fz; s.wyz10 = fy * wz0; s.wyz11 = fy * fz;
    return s;
}
// split one level's packed feature to bf16 hi/lo (cvt.rn.bf16x2 = same rn rounding)
__device__ __forceinline__ void split_feat(unsigned long long a, unsigned& hi, unsigned& lo) {
    float f0, f1; unpack2(a, f0, f1);
    hi = cvt_pack_bf(f0, f1);
    float r0 = f0 - bflo_f(hi);
    float r1 = f1 - bfhi_f(hi);
    lo = cvt_pack_bf(r0, r1);
}

// ---------------- main kernel ----------------
__global__ void __launch_bounds__(128, 4) grid_fused_kernel(
    const float* __restrict__ xyz,
    const float* __restrict__ bound,
    const float* __restrict__ table,
    float* __restrict__ out,
    LevelParams lev, int N)
{
    __shared__ __align__(1024) char smem[SMEM_TOT];   // A tile only (warp-private quarters)
    const uint32_t sb = smem_to_u32(smem);
    const int tid = threadIdx.x;
    const int wid = tid >> 5;
    const int ln  = tid & 31;

    const int half = (N * 8) >> 1;
    int T = blockIdx.x * 128 + tid;          // exact fit: N*8/2 == 8192*128
    int gtA = T, gtB = T + half;
    int pA = gtA >> 3, pB = gtB >> 3;
    int oc = gtA & 7;

    const float b     = bound[0];
    const float inv2b = 1.0f / (2.0f * b);

    float exA, eyA, ezA, wtA, exB, eyB, ezB, wtB;
    setup_item(xyz, b, inv2b, pA, oc, exA, eyA, ezA, wtA);
    setup_item(xyz, b, inv2b, pB, oc, exB, eyB, ezB, wtB);

    const int rowA = wid * 64 + ln;
    const int rowB = rowA + 32;

    // rolling 4-level hi/lo buffers (flushed via STS.128)
    unsigned hiA[4], loA[4], hiB[4], loB[4];

    #pragma unroll
    for (int l = 0; l < NLEV; l++) {
        const float Rf = (float)lev.R[l];
        const unsigned H = lev.H[l];
        const unsigned long long* tab8 =
            reinterpret_cast<const unsigned long long*>(table) + lev.O[l];
        LevWts A = level_setup(Rf, exA, eyA, ezA);
        LevWts B = level_setup(Rf, exB, eyB, ezB);
        unsigned long long aA = 0ull, aB = 0ull;
        if (lev.linear[l]) {
            int s1 = lev.R[l] + 1, s2 = s1 * s1;
            int baseA = A.ix + A.iy * s1 + A.iz * s2;
            int baseB = B.ix + B.iy * s1 + B.iz * s2;
            #pragma unroll
            for (int dx = 0; dx < 2; dx++) {
                float wxdA = dx ? A.fx : A.wx0;
                float wxdB = dx ? B.fx : B.wx0;
                #pragma unroll
                for (int dy = 0; dy < 2; dy++) {
                    #pragma unroll
                    for (int dz = 0; dz < 2; dz++) {
                        int idxA = baseA + dx + dy * s1 + dz * s2;
                        int idxB = baseB + dx + dy * s1 + dz * s2;
                        if (idxA >= (int)H) idxA -= (int)H;
                        if (idxB >= (int)H) idxB -= (int)H;
                        unsigned long long tA = __ldg(tab8 + idxA);
                        unsigned long long tB = __ldg(tab8 + idxB);
                        float wA = wxdA * (dy ? (dz ? A.wyz11 : A.wyz10)
                                              : (dz ? A.wyz01 : A.wyz00));
                        float wB = wxdB * (dy ? (dz ? B.wyz11 : B.wyz10)
                                              : (dz ? B.wyz01 : B.wyz00));
                        ffma2(aA, pack2(wA, wA), tA);
                        ffma2(aB, pack2(wB, wB), tB);
                    }
                }
            }
        } else {
            unsigned mask = H - 1u;
            unsigned hxA0 = (unsigned)A.ix,      hxA1 = hxA0 + 1u;
            unsigned hyA0 = (unsigned)A.iy * P2, hyA1 = hyA0 + P2;
            unsigned hzA0 = (unsigned)A.iz * P3, hzA1 = hzA0 + P3;
            unsigned hxB0 = (unsigned)B.ix,      hxB1 = hxB0 + 1u;
            unsigned hyB0 = (unsigned)B.iy * P2, hyB1 = hyB0 + P2;
            unsigned hzB0 = (unsigned)B.iz * P3, hzB1 = hzB0 + P3;
            #pragma unroll
            for (int dx = 0; dx < 2; dx++) {
                float wxdA = dx ? A.fx : A.wx0;
                float wxdB = dx ? B.fx : B.wx0;
                unsigned hxA = dx ? hxA1 : hxA0;
                unsigned hxB = dx ? hxB1 : hxB0;
                #pragma unroll
                for (int dy = 0; dy < 2; dy++) {
                    unsigned hxyA = hxA ^ (dy ? hyA1 : hyA0);
                    unsigned hxyB = hxB ^ (dy ? hyB1 : hyB0);
                    #pragma unroll
                    for (int dz = 0; dz < 2; dz++) {
                        unsigned idxA = (hxyA ^ (dz ? hzA1 : hzA0)) & mask;
                        unsigned idxB = (hxyB ^ (dz ? hzB1 : hzB0)) & mask;
                        unsigned long long tA = __ldg(tab8 + idxA);
                        unsigned long long tB = __ldg(tab8 + idxB);
                        float wA = wxdA * (dy ? (dz ? A.wyz11 : A.wyz10)
                                              : (dz ? A.wyz01 : A.wyz00));
                        float wB = wxdB * (dy ? (dz ? B.wyz11 : B.wyz10)
                                              : (dz ? B.wyz01 : B.wyz00));
                        ffma2(aA, pack2(wA, wA), tA);
                        ffma2(aB, pack2(wB, wB), tB);
                    }
                }
            }
        }
        split_feat(aA, hiA[l & 3], loA[l & 3]);
        split_feat(aB, hiB[l & 3], loB[l & 3]);
        if ((l & 3) == 3) {
            int q = l >> 2;
            *reinterpret_cast<uint4*>(smem + SW128(rowA * 128 + q * 16)) =
                make_uint4(hiA[0], hiA[1], hiA[2], hiA[3]);
            *reinterpret_cast<uint4*>(smem + SW128(rowA * 128 + 64 + q * 16)) =
                make_uint4(loA[0], loA[1], loA[2], loA[3]);
            *reinterpret_cast<uint4*>(smem + SW128(rowB * 128 + q * 16)) =
                make_uint4(hiB[0], hiB[1], hiB[2], hiB[3]);
            *reinterpret_cast<uint4*>(smem + SW128(rowB * 128 + 64 + q * 16)) =
                make_uint4(loB[0], loB[1], loB[2], loB[3]);
        }
    }
    __syncwarp();

    // ---- w1 fragments: direct from global in fragment order (broadcast-cached) ----
    unsigned b1f[64];
    #pragma unroll
    for (int q = 0; q < 64; q++) b1f[q] = __ldg(&g_f1[q * 32 + ln]);

    // ---- w2 fragments: t-invariant, hoisted before the (non-unrolled) t-loop ----
    unsigned b2h[4][2], b2l[4][2];
    #pragma unroll
    for (int s2 = 0; s2 < 4; s2++) {
        b2h[s2][0] = __ldg(&g_f2[(s2 * 4 + 0) * 32 + ln]);
        b2h[s2][1] = __ldg(&g_f2[(s2 * 4 + 1) * 32 + ln]);
        b2l[s2][0] = __ldg(&g_f2[(s2 * 4 + 2) * 32 + ln]);
        b2l[s2][1] = __ldg(&g_f2[(s2 * 4 + 3) * 32 + ln]);
    }

    const int baseAI = blockIdx.x * 128 + wid * 32;   // global item idx of warp row 0

    #pragma unroll 1
    for (int t = 0; t < 4; t++) {        // runtime loop: shrink I-footprint ~12KB
        // A1 fragments for this mtile (hi/lo x 2 ksteps)
        unsigned ahi[2][4], alo[2][4];
        #pragma unroll
        for (int s = 0; s < 2; s++) {
            int mat = ln >> 3;
            uint32_t row  = wid * 64 + t * 16 + (mat & 1) * 8 + (ln & 7);
            uint32_t byteh = s * 32 + (mat >> 1) * 16;
            ldsm_x4(ahi[s][0], ahi[s][1], ahi[s][2], ahi[s][3],
                    sb + SW128(row * 128 + byteh));
            ldsm_x4(alo[s][0], alo[s][1], alo[s][2], alo[s][3],
                    sb + SW128(row * 128 + 64 + byteh));
        }
        float wsrc = (t < 2) ? wtA : wtB;
        int tq = (t & 1) * 16;
        float wt0 = __shfl_sync(0xffffffffu, wsrc, tq + (ln >> 2));
        float wt1 = __shfl_sync(0xffffffffu, wsrc, tq + 8 + (ln >> 2));

        float D2[4] = {0.f, 0.f, 0.f, 0.f};
        #pragma unroll
        for (int s2 = 0; s2 < 4; s2++) {     // gemm2 kstep == gemm1 ntile pair
            unsigned a2hi[4], a2lo[4];
            #pragma unroll
            for (int e = 0; e < 2; e++) {
                int nt = 2 * s2 + e;
                float D1[4] = {0.f, 0.f, 0.f, 0.f};
                mma_bf16(D1, ahi[0], &b1f[nt * 8 + 0]);   // hi*hi  (term0,s0)
                mma_bf16(D1, ahi[1], &b1f[nt * 8 + 2]);   //        (term0,s1)
                mma_bf16(D1, ahi[0], &b1f[nt * 8 + 4]);   // hi*lo  (term1,s0)
                mma_bf16(D1, ahi[1], &b1f[nt * 8 + 6]);   //        (term1,s1)
                mma_bf16(D1, alo[0], &b1f[nt * 8 + 0]);   // lo*hi  (term0,s0)
                mma_bf16(D1, alo[1], &b1f[nt * 8 + 2]);   //        (term0,s1)
                float h0 = fmaxf(D1[0], 0.f) * wt0;
                float h1 = fmaxf(D1[1], 0.f) * wt0;
                float h2 = fmaxf(D1[2], 0.f) * wt1;
                float h3 = fmaxf(D1[3], 0.f) * wt1;
                unsigned p01 = cvt_pack_bf(h0, h1);
                unsigned p23 = cvt_pack_bf(h2, h3);
                a2hi[2 * e + 0] = p01;
                a2hi[2 * e + 1] = p23;
                a2lo[2 * e + 0] = cvt_pack_bf(h0 - bflo_f(p01), h1 - bfhi_f(p01));
                a2lo[2 * e + 1] = cvt_pack_bf(h2 - bflo_f(p23), h3 - bfhi_f(p23));
            }
            mma_bf16(D2, a2hi, b2h[s2]);
            mma_bf16(D2, a2hi, b2l[s2]);
            mma_bf16(D2, a2lo, b2h[s2]);
        }

        // reduce the 8 corner-rows (quads hold distinct rows; cols preserved)
        #pragma unroll
        for (int k = 0; k < 4; k++) {
            D2[k] += __shfl_xor_sync(0xffffffffu, D2[k], 4);
            D2[k] += __shfl_xor_sync(0xffffffffu, D2[k], 8);
            D2[k] += __shfl_xor_sync(0xffffffffu, D2[k], 16);
        }
        int obase = (t < 2) ? (baseAI + 16 * t) : (baseAI + half + 16 * (t - 2));
        if (ln < 4) {
            *reinterpret_cast<float2*>(out + obase + 2 * ln) = make_float2(D2[0], D2[1]);
        } else if (ln < 8) {
            *reinterpret_cast<float2*>(out + obase + 8 + 2 * (ln - 4)) = make_float2(D2[2], D2[3]);
        }
    }
}

extern "C" void kernel_launch(void* const* d_in, const int* in_sizes, int n_in,
                              void* d_out, int out_size)
{
    const float* xyz   = (const float*)d_in[0];
    const float* bound = (const float*)d_in[1];
    const float* table = (const float*)d_in[2];
    const float* w1    = (const float*)d_in[3];
    const float* w2    = (const float*)d_in[4];
    float* out = (float*)d_out;

    int N = in_sizes[0] / 3;

    prep_weights_kernel<<<10, 256>>>(w1, w2);

    // torch-ngp level construction (exact numpy double math)
    LevelParams lev;
    double scale = exp2(log2(513.0 / 16.0) / 15.0);
    long long off = 0;
    for (int i = 0; i < NLEV; i++) {
        int res = (int)ceil(16.0 * pow(scale, (double)i));
        long long cube = (long long)(res + 1) * (res + 1) * (res + 1);
        long long n = cube;
        if (n > (1LL << 19)) n = (1LL << 19);
        n = ((n + 7) / 8) * 8;
        lev.R[i] = res;
        lev.H[i] = (unsigned)n;
        lev.O[i] = (int)off;
        lev.linear[i] = (cube <= n) ? 1 : 0;
        off += n;
    }

    int half = (N * 8) / 2;
    int blocks = (half + 127) / 128;
    grid_fused_kernel<<<blocks, 128>>>(xyz, bound, table, out, lev, N);
}

// round 15
// speedup vs baseline: 1.1535x; 1.1535x over previous
#include <cuda_runtime.h>
#include <cuda_bf16.h>
#include <math.h>
#include <stdint.h>

#define NLEV 16
#define P2 2654435761u
#define P3 805459861u

struct LevelParams {
    int          R[NLEV];
    unsigned int H[NLEV];
    int          O[NLEV];
    int          linear[NLEV];
};

// Weights pre-arranged in mma FRAGMENT order by the prep kernel.
__device__ __align__(16) unsigned g_f1[2048];
__device__ __align__(16) unsigned g_f2[512];

// smem: A tile only, 256 rows x 128B (warp-private quarters)
#define SMEM_TOT 32768
#define SW128(o) ((o) ^ (((o) >> 3) & 0x70))

// ---------------- helpers ----------------
__device__ __forceinline__ uint32_t smem_to_u32(const void* p) {
    uint32_t a;
    asm("{ .reg .u64 t; cvta.to.shared.u64 t, %1; cvt.u32.u64 %0, t; }" : "=r"(a) : "l"(p));
    return a;
}
__device__ __forceinline__ unsigned long long pack2(float lo, float hi) {
    unsigned long long r;
    asm("mov.b64 %0, {%1, %2};" : "=l"(r) : "f"(lo), "f"(hi));
    return r;
}
__device__ __forceinline__ void unpack2(unsigned long long v, float &lo, float &hi) {
    asm("mov.b64 {%0, %1}, %2;" : "=f"(lo), "=f"(hi) : "l"(v));
}
__device__ __forceinline__ void ffma2(unsigned long long &d, unsigned long long a, unsigned long long b) {
    asm("fma.rn.f32x2 %0, %1, %2, %0;" : "+l"(d) : "l"(a), "l"(b));
}
// packed lerp: a + f*(b - a)
__device__ __forceinline__ unsigned long long lerp2(
    unsigned long long a, unsigned long long b, unsigned long long f2, unsigned long long neg1)
{
    unsigned long long d = b; ffma2(d, neg1, a);   // d = b - a
    unsigned long long r = a; ffma2(r, f2, d);     // r = a + f*d
    return r;
}
__device__ __forceinline__ unsigned packbf(__nv_bfloat16 a, __nv_bfloat16 b) {
    __nv_bfloat162 t = __halves2bfloat162(a, b);
    unsigned r; memcpy(&r, &t, 4); return r;
}
__device__ __forceinline__ unsigned cvt_pack_bf(float lo, float hi) {
    unsigned r;
    asm("cvt.rn.bf16x2.f32 %0, %1, %2;" : "=r"(r) : "f"(hi), "f"(lo));
    return r;
}
__device__ __forceinline__ float bflo_f(unsigned u) { return __uint_as_float(u << 16); }
__device__ __forceinline__ float bfhi_f(unsigned u) { return __uint_as_float(u & 0xffff0000u); }

__device__ __forceinline__ void ldsm_x4(unsigned& r0, unsigned& r1, unsigned& r2, unsigned& r3, uint32_t a) {
    asm volatile("ldmatrix.sync.aligned.m8n8.x4.shared.b16 {%0,%1,%2,%3}, [%4];"
        : "=r"(r0), "=r"(r1), "=r"(r2), "=r"(r3) : "r"(a));
}
__device__ __forceinline__ void mma_bf16(float* d, const unsigned* a, const unsigned* b) {
    asm volatile("mma.sync.aligned.m16n8k16.row.col.f32.bf16.bf16.f32 "
        "{%0,%1,%2,%3}, {%4,%5,%6,%7}, {%8,%9}, {%0,%1,%2,%3};"
        : "+f"(d[0]), "+f"(d[1]), "+f"(d[2]), "+f"(d[3])
        : "r"(a[0]), "r"(a[1]), "r"(a[2]), "r"(a[3]), "r"(b[0]), "r"(b[1]));
}

// ---------------- prep kernel: emit weights in fragment order ----------------
__global__ void prep_weights_kernel(const float* __restrict__ w1,
                                    const float* __restrict__ w2) {
    int i = blockIdx.x * 256 + threadIdx.x;
    if (i < 2048) {
        int q = i >> 5, ln = i & 31;
        int nt = q >> 3, term = (q >> 2) & 1, s = (q >> 1) & 1, r = q & 1;
        int j  = nt * 8 + (ln >> 2);
        int k0 = 16 * s + 8 * r + (ln & 3) * 2;
        float v0 = w1[k0 * 64 + j];
        float v1 = w1[(k0 + 1) * 64 + j];
        __nv_bfloat16 h0 = __float2bfloat16(v0), h1 = __float2bfloat16(v1);
        unsigned rr;
        if (!term) rr = packbf(h0, h1);
        else rr = packbf(__float2bfloat16(v0 - __bfloat162float(h0)),
                         __float2bfloat16(v1 - __bfloat162float(h1)));
        g_f1[i] = rr;
    } else if (i < 2560) {
        int k2 = i - 2048;
        int q = k2 >> 5, ln = k2 & 31;
        int s2 = q >> 2, term = (q >> 1) & 1, r = q & 1;
        int n  = ln >> 2;
        int k0 = 16 * s2 + 8 * r + (ln & 3) * 2;
        float v0 = w2[k0 * 8 + n];
        float v1 = w2[(k0 + 1) * 8 + n];
        __nv_bfloat16 h0 = __float2bfloat16(v0), h1 = __float2bfloat16(v1);
        unsigned rr;
        if (!term) rr = packbf(h0, h1);
        else rr = packbf(__float2bfloat16(v0 - __bfloat162float(h0)),
                         __float2bfloat16(v1 - __bfloat162float(h1)));
        g_f2[k2] = rr;
    }
}

// ---------------- encode helpers ----------------
__device__ __forceinline__ void setup_item(
    const float* __restrict__ xyz, float b, float inv2b, int p, int oc,
    float& ex, float& ey, float& ez, float& wt)
{
    float cx = (xyz[3 * p + 0] + b) * inv2b * 512.0f;
    float cy = (xyz[3 * p + 1] + b) * inv2b * 512.0f;
    float cz = (xyz[3 * p + 2] + b) * inv2b * 512.0f;
    int c0x = min(max((int)floorf(cx), 0), 511);
    int c0y = min(max((int)floorf(cy), 0), 511);
    int c0z = min(max((int)floorf(cz), 0), 511);
    float u = cx - (float)c0x, v = cy - (float)c0y, w = cz - (float)c0z;
    int ox = (oc >> 2) & 1, oy = (oc >> 1) & 1, oz = oc & 1;
    wt = (ox ? u : 1.0f - u) * (oy ? v : 1.0f - v) * (oz ? w : 1.0f - w);
    ex = (float)(c0x + ox) * (1.0f / 512.0f);
    ey = (float)(c0y + oy) * (1.0f / 512.0f);
    ez = (float)(c0z + oz) * (1.0f / 512.0f);
}
struct Cell { int ix, iy, iz; float fx, fy, fz; };
__device__ __forceinline__ Cell cell_setup(float Rf, float ex, float ey, float ez) {
    Cell c;
    float px = ex * Rf + 0.5f, py = ey * Rf + 0.5f, pz = ez * Rf + 0.5f;
    float gx = floorf(px), gy = floorf(py), gz = floorf(pz);
    c.ix = (int)gx; c.iy = (int)gy; c.iz = (int)gz;
    c.fx = px - gx; c.fy = py - gy; c.fz = pz - gz;
    return c;
}
__device__ __forceinline__ void split_feat(unsigned long long a, unsigned& hi, unsigned& lo) {
    float f0, f1; unpack2(a, f0, f1);
    hi = cvt_pack_bf(f0, f1);
    lo = cvt_pack_bf(f0 - bflo_f(hi), f1 - bfhi_f(hi));
}
// tree-lerp 8 corners (t[dx*4+dy*2+dz]) -> packed feature
__device__ __forceinline__ unsigned long long interp8(
    const unsigned long long* t, const Cell& c, unsigned long long neg1)
{
    unsigned long long fz2 = pack2(c.fz, c.fz);
    unsigned long long fy2 = pack2(c.fy, c.fy);
    unsigned long long fx2 = pack2(c.fx, c.fx);
    unsigned long long z00 = lerp2(t[0], t[1], fz2, neg1);
    unsigned long long z01 = lerp2(t[2], t[3], fz2, neg1);
    unsigned long long z10 = lerp2(t[4], t[5], fz2, neg1);
    unsigned long long z11 = lerp2(t[6], t[7], fz2, neg1);
    unsigned long long y0  = lerp2(z00, z01, fy2, neg1);
    unsigned long long y1  = lerp2(z10, z11, fy2, neg1);
    return lerp2(y0, y1, fx2, neg1);
}

// ---------------- main kernel ----------------
template <bool SPEC>
__global__ void __launch_bounds__(128, 4) grid_fused_kernel(
    const float* __restrict__ xyz,
    const float* __restrict__ bound,
    const float* __restrict__ table,
    float* __restrict__ out,
    LevelParams lev, int N)
{
    // Function-local constexpr level table: folds to immediates under the
    // fully-unrolled level loop when SPEC==true. (Verified: cumsum == 5295344;
    // host recomputes with exact double math and falls back on mismatch.)
    constexpr int      k_R[NLEV]   = {16,21,26,33,41,51,65,81,102,129,162,204,257,324,408,513};
    constexpr unsigned k_H[NLEV]   = {4920u,10648u,19688u,39304u,74088u,140608u,287496u,
                                      524288u,524288u,524288u,524288u,524288u,524288u,524288u,524288u,524288u};
    constexpr int      k_O[NLEV]   = {0,4920,15568,35256,74560,148648,289256,576752,
                                      1101040,1625328,2149616,2673904,3198192,3722480,4246768,4771056};
    constexpr int      k_LIN[NLEV] = {1,1,1,1,1,1,1,0,0,0,0,0,0,0,0,0};

    __shared__ __align__(1024) char smem[SMEM_TOT];
    const uint32_t sb = smem_to_u32(smem);
    const int tid = threadIdx.x;
    const int wid = tid >> 5;
    const int ln  = tid & 31;

    const int half = (N * 8) >> 1;
    int T = blockIdx.x * 128 + tid;
    int gtA = T, gtB = T + half;
    int pA = gtA >> 3, pB = gtB >> 3;
    int oc = gtA & 7;

    const float b     = bound[0];
    const float inv2b = 1.0f / (2.0f * b);

    float exA, eyA, ezA, wtA, exB, eyB, ezB, wtB;
    setup_item(xyz, b, inv2b, pA, oc, exA, eyA, ezA, wtA);
    setup_item(xyz, b, inv2b, pB, oc, exB, eyB, ezB, wtB);

    const int rowA = wid * 64 + ln;
    const int rowB = rowA + 32;
    const unsigned long long NEG1 = pack2(-1.0f, -1.0f);

    unsigned hiA[4], loA[4], hiB[4], loB[4];   // rolling 4-level hi/lo buffers

    #pragma unroll
    for (int l = 0; l < NLEV; l++) {
        const int      R   = SPEC ? k_R[l]   : lev.R[l];
        const unsigned H   = SPEC ? k_H[l]   : lev.H[l];
        const int      O   = SPEC ? k_O[l]   : lev.O[l];
        const bool     LIN = SPEC ? (k_LIN[l] != 0) : (lev.linear[l] != 0);
        const float Rf = (float)R;
        const unsigned long long* tab8 =
            reinterpret_cast<const unsigned long long*>(table) + O;

        Cell A = cell_setup(Rf, exA, eyA, ezA);
        Cell B = cell_setup(Rf, exB, eyB, ezB);

        unsigned long long tA[8], tB[8];

        if (LIN) {
            int s1 = R + 1, s2 = s1 * s1;
            int baseA = A.ix + A.iy * s1 + A.iz * s2;
            int baseB = B.ix + B.iy * s1 + B.iz * s2;
            #pragma unroll
            for (int dx = 0; dx < 2; dx++)
                #pragma unroll
                for (int dy = 0; dy < 2; dy++)
                    #pragma unroll
                    for (int dz = 0; dz < 2; dz++) {
                        int idxA = baseA + dx + dy * s1 + dz * s2;
                        int idxB = baseB + dx + dy * s1 + dz * s2;
                        if (idxA >= (int)H) idxA -= (int)H;   // idx < 2H provable
                        if (idxB >= (int)H) idxB -= (int)H;
                        tA[dx * 4 + dy * 2 + dz] = __ldg(tab8 + idxA);
                        tB[dx * 4 + dy * 2 + dz] = __ldg(tab8 + idxB);
                    }
        } else {
            unsigned mask = H - 1u;                 // 2^19 for hashed levels
            unsigned hxA0 = (unsigned)A.ix,      hxA1 = hxA0 + 1u;
            unsigned hyA0 = (unsigned)A.iy * P2, hyA1 = hyA0 + P2;
            unsigned hzA0 = (unsigned)A.iz * P3, hzA1 = hzA0 + P3;
            unsigned hxB0 = (unsigned)B.ix,      hxB1 = hxB0 + 1u;
            unsigned hyB0 = (unsigned)B.iy * P2, hyB1 = hyB0 + P2;
            unsigned hzB0 = (unsigned)B.iz * P3, hzB1 = hzB0 + P3;
            #pragma unroll
            for (int dx = 0; dx < 2; dx++) {
                unsigned hxA = dx ? hxA1 : hxA0;
                unsigned hxB = dx ? hxB1 : hxB0;
                #pragma unroll
                for (int dy = 0; dy < 2; dy++) {
                    unsigned hxyA = hxA ^ (dy ? hyA1 : hyA0);
                    unsigned hxyB = hxB ^ (dy ? hyB1 : hyB0);
                    #pragma unroll
                    for (int dz = 0; dz < 2; dz++) {
                        unsigned idxA = (hxyA ^ (dz ? hzA1 : hzA0)) & mask;
                        unsigned idxB = (hxyB ^ (dz ? hzB1 : hzB0)) & mask;
                        tA[dx * 4 + dy * 2 + dz] = __ldg(tab8 + idxA);
                        tB[dx * 4 + dy * 2 + dz] = __ldg(tab8 + idxB);
                    }
                }
            }
        }

        unsigned long long aA = interp8(tA, A, NEG1);
        unsigned long long aB = interp8(tB, B, NEG1);

        split_feat(aA, hiA[l & 3], loA[l & 3]);
        split_feat(aB, hiB[l & 3], loB[l & 3]);
        if ((l & 3) == 3) {
            int q = l >> 2;
            *reinterpret_cast<uint4*>(smem + SW128(rowA * 128 + q * 16)) =
                make_uint4(hiA[0], hiA[1], hiA[2], hiA[3]);
            *reinterpret_cast<uint4*>(smem + SW128(rowA * 128 + 64 + q * 16)) =
                make_uint4(loA[0], loA[1], loA[2], loA[3]);
            *reinterpret_cast<uint4*>(smem + SW128(rowB * 128 + q * 16)) =
                make_uint4(hiB[0], hiB[1], hiB[2], hiB[3]);
            *reinterpret_cast<uint4*>(smem + SW128(rowB * 128 + 64 + q * 16)) =
                make_uint4(loB[0], loB[1], loB[2], loB[3]);
        }
    }
    __syncwarp();

    // ---- w1 fragments: direct from global in fragment order (broadcast-cached) ----
    unsigned b1f[64];
    #pragma unroll
    for (int q = 0; q < 64; q++) b1f[q] = __ldg(&g_f1[q * 32 + ln]);

    // ---- w2 fragments: t-invariant, hoisted ----
    unsigned b2h[4][2], b2l[4][2];
    #pragma unroll
    for (int s2 = 0; s2 < 4; s2++) {
        b2h[s2][0] = __ldg(&g_f2[(s2 * 4 + 0) * 32 + ln]);
        b2h[s2][1] = __ldg(&g_f2[(s2 * 4 + 1) * 32 + ln]);
        b2l[s2][0] = __ldg(&g_f2[(s2 * 4 + 2) * 32 + ln]);
        b2l[s2][1] = __ldg(&g_f2[(s2 * 4 + 3) * 32 + ln]);
    }

    const int baseAI = blockIdx.x * 128 + wid * 32;

    #pragma unroll 1
    for (int t = 0; t < 4; t++) {
        unsigned ahi[2][4], alo[2][4];
        #pragma unroll
        for (int s = 0; s < 2; s++) {
            int mat = ln >> 3;
            uint32_t row  = wid * 64 + t * 16 + (mat & 1) * 8 + (ln & 7);
            uint32_t byteh = s * 32 + (mat >> 1) * 16;
            ldsm_x4(ahi[s][0], ahi[s][1], ahi[s][2], ahi[s][3],
                    sb + SW128(row * 128 + byteh));
            ldsm_x4(alo[s][0], alo[s][1], alo[s][2], alo[s][3],
                    sb + SW128(row * 128 + 64 + byteh));
        }
        float wsrc = (t < 2) ? wtA : wtB;
        int tq = (t & 1) * 16;
        float wt0 = __shfl_sync(0xffffffffu, wsrc, tq + (ln >> 2));
        float wt1 = __shfl_sync(0xffffffffu, wsrc, tq + 8 + (ln >> 2));

        float D2[4] = {0.f, 0.f, 0.f, 0.f};
        #pragma unroll
        for (int s2 = 0; s2 < 4; s2++) {
            unsigned a2hi[4], a2lo[4];
            #pragma unroll
            for (int e = 0; e < 2; e++) {
                int nt = 2 * s2 + e;
                float D1[4] = {0.f, 0.f, 0.f, 0.f};
                mma_bf16(D1, ahi[0], &b1f[nt * 8 + 0]);
                mma_bf16(D1, ahi[1], &b1f[nt * 8 + 2]);
                mma_bf16(D1, ahi[0], &b1f[nt * 8 + 4]);
                mma_bf16(D1, ahi[1], &b1f[nt * 8 + 6]);
                mma_bf16(D1, alo[0], &b1f[nt * 8 + 0]);
                mma_bf16(D1, alo[1], &b1f[nt * 8 + 2]);
                float h0 = fmaxf(D1[0], 0.f) * wt0;
                float h1 = fmaxf(D1[1], 0.f) * wt0;
                float h2 = fmaxf(D1[2], 0.f) * wt1;
                float h3 = fmaxf(D1[3], 0.f) * wt1;
                unsigned p01 = cvt_pack_bf(h0, h1);
                unsigned p23 = cvt_pack_bf(h2, h3);
                a2hi[2 * e + 0] = p01;
                a2hi[2 * e + 1] = p23;
                a2lo[2 * e + 0] = cvt_pack_bf(h0 - bflo_f(p01), h1 - bfhi_f(p01));
                a2lo[2 * e + 1] = cvt_pack_bf(h2 - bflo_f(p23), h3 - bfhi_f(p23));
            }
            mma_bf16(D2, a2hi, b2h[s2]);
            mma_bf16(D2, a2hi, b2l[s2]);
            mma_bf16(D2, a2lo, b2h[s2]);
        }

        #pragma unroll
        for (int k = 0; k < 4; k++) {
            D2[k] += __shfl_xor_sync(0xffffffffu, D2[k], 4);
            D2[k] += __shfl_xor_sync(0xffffffffu, D2[k], 8);
            D2[k] += __shfl_xor_sync(0xffffffffu, D2[k], 16);
        }
        int obase = (t < 2) ? (baseAI + 16 * t) : (baseAI + half + 16 * (t - 2));
        if (ln < 4) {
            *reinterpret_cast<float2*>(out + obase + 2 * ln) = make_float2(D2[0], D2[1]);
        } else if (ln < 8) {
            *reinterpret_cast<float2*>(out + obase + 8 + 2 * (ln - 4)) = make_float2(D2[2], D2[3]);
        }
    }
}

extern "C" void kernel_launch(void* const* d_in, const int* in_sizes, int n_in,
                              void* d_out, int out_size)
{
    const float* xyz   = (const float*)d_in[0];
    const float* bound = (const float*)d_in[1];
    const float* table = (const float*)d_in[2];
    const float* w1    = (const float*)d_in[3];
    const float* w2    = (const float*)d_in[4];
    float* out = (float*)d_out;

    // Host copy of the hardcoded table for verification.
    static const int      h_R[NLEV]   = {16,21,26,33,41,51,65,81,102,129,162,204,257,324,408,513};
    static const unsigned h_H[NLEV]   = {4920u,10648u,19688u,39304u,74088u,140608u,287496u,
                                         524288u,524288u,524288u,524288u,524288u,524288u,524288u,524288u,524288u};
    static const int      h_O[NLEV]   = {0,4920,15568,35256,74560,148648,289256,576752,
                                         1101040,1625328,2149616,2673904,3198192,3722480,4246768,4771056};
    static const int      h_LIN[NLEV] = {1,1,1,1,1,1,1,0,0,0,0,0,0,0,0,0};

    int N = in_sizes[0] / 3;

    prep_weights_kernel<<<10, 256>>>(w1, w2);

    // torch-ngp level construction (exact numpy double math) + verify vs hardcoded table
    LevelParams lev;
    double scale = exp2(log2(513.0 / 16.0) / 15.0);
    long long off = 0;
    bool match = true;
    for (int i = 0; i < NLEV; i++) {
        int res = (int)ceil(16.0 * pow(scale, (double)i));
        long long cube = (long long)(res + 1) * (res + 1) * (res + 1);
        long long n = cube;
        if (n > (1LL << 19)) n = (1LL << 19);
        n = ((n + 7) / 8) * 8;
        lev.R[i] = res;
        lev.H[i] = (unsigned)n;
        lev.O[i] = (int)off;
        lev.linear[i] = (cube <= n) ? 1 : 0;
        off += n;
        match = match && (lev.R[i] == h_R[i]) && (lev.H[i] == h_H[i])
                      && (lev.O[i] == h_O[i]) && (lev.linear[i] == h_LIN[i]);
    }

    int half = (N * 8) / 2;
    int blocks = (half + 127) / 128;
    if (match)
        grid_fused_kernel<true><<<blocks, 128>>>(xyz, bound, table, out, lev, N);
    else
        grid_fused_kernel<false><<<blocks, 128>>>(xyz, bound, table, out, lev, N);
}